// round 4
// baseline (speedup 1.0000x reference)
#include <cuda_runtime.h>
#include <cuda_fp16.h>
#include <cstdint>

// LinearAttend: q,k,v [4][8][64][8192] f32 -> out same shape.
//   ks = softmax(k, axis=s); qs = softmax(q, axis=d) * D^-0.5
//   ctx = ks @ v^T (64x64/head); out = ctx^T @ qs
// fp16 m16n8k16 MMA (fp32 accum), ldmatrix feed, ex2.approx.f16x2 exps in
// ctx, Zk computed by the MMA itself via a ones-column, pre-normalized half
// context, deferred/folded normalizations.

#define SQ 8192
#define DH 64
#define NHEADS 32
#define CHUNKS 32
#define CHUNK_S (SQ / CHUNKS)    // 256 -> 4 tiles of 64
#define LOG2E 1.4426950408889634f

__device__ float  g_ctx[NHEADS * DH * DH];   // fp32 accumulation scratch
__device__ float  g_zk[NHEADS * DH];         // sum_s exp(k[i,s])
__device__ __half g_ctxh[NHEADS * DH * DH];  // normalized half context

__device__ __forceinline__ uint32_t smem_u32(const void* p) {
    return (uint32_t)__cvta_generic_to_shared(p);
}
__device__ __forceinline__ void ldsm_x4(uint32_t* r, uint32_t a) {
    asm volatile("ldmatrix.sync.aligned.m8n8.x4.shared.b16 {%0,%1,%2,%3}, [%4];"
                 : "=r"(r[0]), "=r"(r[1]), "=r"(r[2]), "=r"(r[3]) : "r"(a));
}
__device__ __forceinline__ void ldsm_x2(uint32_t* r, uint32_t a) {
    asm volatile("ldmatrix.sync.aligned.m8n8.x2.shared.b16 {%0,%1}, [%2];"
                 : "=r"(r[0]), "=r"(r[1]) : "r"(a));
}
__device__ __forceinline__ void ldsm_x4t(uint32_t* r, uint32_t a) {
    asm volatile("ldmatrix.sync.aligned.m8n8.x4.trans.shared.b16 {%0,%1,%2,%3}, [%4];"
                 : "=r"(r[0]), "=r"(r[1]), "=r"(r[2]), "=r"(r[3]) : "r"(a));
}
__device__ __forceinline__ void mma_f16(float* d, const uint32_t* a, const uint32_t* b) {
    asm volatile(
        "mma.sync.aligned.m16n8k16.row.col.f32.f16.f16.f32 "
        "{%0,%1,%2,%3}, {%4,%5,%6,%7}, {%8,%9}, {%0,%1,%2,%3};"
        : "+f"(d[0]), "+f"(d[1]), "+f"(d[2]), "+f"(d[3])
        : "r"(a[0]), "r"(a[1]), "r"(a[2]), "r"(a[3]), "r"(b[0]), "r"(b[1]));
}
__device__ __forceinline__ uint32_t pack_h2(float hi, float lo) {
    uint32_t h;
    asm("cvt.rn.f16x2.f32 %0, %1, %2;" : "=r"(h) : "f"(hi), "f"(lo));
    return h;
}
__device__ __forceinline__ uint32_t ex2_h2(uint32_t y) {
    uint32_t r;
    asm("ex2.approx.f16x2 %0, %1;" : "=r"(r) : "r"(y));
    return r;
}

// ---------------------------------------------------------------------------
// Kernel 1: ctx[i][j] += sum_{s} exp(k[i,s]) * v[j,s]; Zk via ones-column MMA.
// grid (CHUNKS, NHEADS), block 128 (4 warps; warp = i-block of 16 rows).
// ---------------------------------------------------------------------------
__global__ __launch_bounds__(128) void ctx_kernel(const float* __restrict__ k,
                                                  const float* __restrict__ v) {
    __shared__ __half sA[64][72];   // exp(k) half   [i][s]
    __shared__ __half sB[72][72];   // v half        [j][s]; rows 64..71: ones/zeros

    const int head = blockIdx.y;
    const int s0   = blockIdx.x * CHUNK_S;
    const int tid  = threadIdx.x;
    const int warp = tid >> 5;
    const int lane = tid & 31;

    const float* kg = k + (size_t)head * DH * SQ;
    const float* vg = v + (size_t)head * DH * SQ;

    // rows 64..71 of B: row 64 = 1.0h (Zk column), rows 65..71 = 0
    for (int e = tid; e < 8 * 36; e += 128) {
        const int row = 64 + e / 36;
        *reinterpret_cast<uint32_t*>(&sB[row][(e % 36) * 2]) =
            (row == 64) ? 0x3C003C00u : 0u;
    }

    float acc[9][4];
#pragma unroll
    for (int n = 0; n < 9; ++n)
#pragma unroll
        for (int c = 0; c < 4; ++c) acc[n][c] = 0.0f;

    const int r  = tid >> 4;         // 0..7
    const int c4 = (tid & 15) * 4;   // 0..60

    float4 kreg[8], vreg[8];
    int scol = s0 + c4;
#pragma unroll
    for (int ib = 0; ib < 8; ++ib) {
        const size_t off = (size_t)(ib * 8 + r) * SQ + scol;
        kreg[ib] = *reinterpret_cast<const float4*>(kg + off);
        vreg[ib] = *reinterpret_cast<const float4*>(vg + off);
    }

    const int ntiles = CHUNK_S / 64;
    for (int t = 0; t < ntiles; ++t) {
#pragma unroll
        for (int ib = 0; ib < 8; ++ib) {
            const int i = ib * 8 + r;
            uint2 ek;
            ek.x = ex2_h2(pack_h2(kreg[ib].y * LOG2E, kreg[ib].x * LOG2E));
            ek.y = ex2_h2(pack_h2(kreg[ib].w * LOG2E, kreg[ib].z * LOG2E));
            *reinterpret_cast<uint2*>(&sA[i][c4]) = ek;
            uint2 vv;
            vv.x = pack_h2(vreg[ib].y, vreg[ib].x);
            vv.y = pack_h2(vreg[ib].w, vreg[ib].z);
            *reinterpret_cast<uint2*>(&sB[i][c4]) = vv;
        }
        __syncthreads();

        if (t + 1 < ntiles) {
            scol += 64;
#pragma unroll
            for (int ib = 0; ib < 8; ++ib) {
                const size_t off = (size_t)(ib * 8 + r) * SQ + scol;
                kreg[ib] = *reinterpret_cast<const float4*>(kg + off);
                vreg[ib] = *reinterpret_cast<const float4*>(vg + off);
            }
        }

#pragma unroll
        for (int kk = 0; kk < 4; ++kk) {
            uint32_t a[4];
            ldsm_x4(a, smem_u32(&sA[warp * 16 + (lane & 15)]
                                  [kk * 16 + (lane >> 4) * 8]));
#pragma unroll
            for (int np = 0; np < 4; ++np) {   // n-block pairs (0,1)..(6,7)
                uint32_t b[4];
                ldsm_x4(b, smem_u32(&sB[(np * 2 + (lane >> 4)) * 8 + (lane & 7)]
                                      [kk * 16 + ((lane >> 3) & 1) * 8]));
                mma_f16(acc[np * 2],     a, b);
                mma_f16(acc[np * 2 + 1], a, b + 2);
            }
            uint32_t b2[2];                    // ones block (j=64..71)
            ldsm_x2(b2, smem_u32(&sB[64 + (lane & 7)]
                                   [kk * 16 + ((lane >> 3) & 1) * 8]));
            mma_f16(acc[8], a, b2);
        }
        __syncthreads();
    }

    float* ctx = g_ctx + head * DH * DH;
    const int i0 = warp * 16 + (lane >> 2);
    const int j0 = (lane & 3) * 2;
#pragma unroll
    for (int n = 0; n < 8; ++n) {
        const int j = n * 8 + j0;
        atomicAdd(&ctx[i0 * 64 + j],           acc[n][0]);
        atomicAdd(&ctx[i0 * 64 + j + 1],       acc[n][1]);
        atomicAdd(&ctx[(i0 + 8) * 64 + j],     acc[n][2]);
        atomicAdd(&ctx[(i0 + 8) * 64 + j + 1], acc[n][3]);
    }
    if ((lane & 3) == 0) {                     // col 64 = Zk
        atomicAdd(&g_zk[head * 64 + i0],     acc[8][0]);
        atomicAdd(&g_zk[head * 64 + i0 + 8], acc[8][2]);
    }
}

// ---------------------------------------------------------------------------
// Kernel 1.5: normalize context to half:  ctxh[i][j] = ctx[i][j]*0.125/Zk[i]
// grid 32 (one CTA per head), block 128.
// ---------------------------------------------------------------------------
__global__ __launch_bounds__(128) void norm_kernel() {
    const int head = blockIdx.x;
    const int tid  = threadIdx.x;
    const float* ctx = g_ctx + head * DH * DH;
    __half* och = g_ctxh + head * DH * DH;

    const int base = tid * 32;                  // half a row per thread
    const float inv = __fdividef(0.125f, g_zk[head * 64 + (base >> 6)]);
#pragma unroll
    for (int p = 0; p < 4; ++p) {
        float4 a = *reinterpret_cast<const float4*>(ctx + base + p * 8);
        float4 b = *reinterpret_cast<const float4*>(ctx + base + p * 8 + 4);
        uint4 o;
        o.x = pack_h2(a.y * inv, a.x * inv);
        o.y = pack_h2(a.w * inv, a.z * inv);
        o.z = pack_h2(b.y * inv, b.x * inv);
        o.w = pack_h2(b.w * inv, b.z * inv);
        *reinterpret_cast<uint4*>(och + base + p * 8) = o;
    }
}

// ---------------------------------------------------------------------------
// Kernel 2: out[j,s] = (1/Zq_s) * sum_i ctxh[i][j] * exp(q[i,s])
// grid (SQ/256, NHEADS), block 512. Tile 64 j x 256 s.
// ---------------------------------------------------------------------------
__global__ __launch_bounds__(512) void out_kernel(const float* __restrict__ q,
                                                  float* __restrict__ out) {
    __shared__ __half sCt[64][72];     // [i][j] normalized half context
    __shared__ __half sQ[64][264];     // [i][s] exp(q)
    __shared__ float sZp[8][260];      // per-thread-row Zq partials
    __shared__ float sCs[256];         // 1/Zq_s

    const int head = blockIdx.y;
    const int s0   = blockIdx.x * 256;
    const int tid  = threadIdx.x;
    const int warp = tid >> 5;
    const int lane = tid & 31;

    const float* qg = q + (size_t)head * DH * SQ + s0;
    const int r  = tid >> 6;           // 0..7
    const int c4 = (tid & 63) * 4;     // 0..252

    // issue all global loads first
    float4 qreg[8];
#pragma unroll
    for (int ib = 0; ib < 8; ++ib) {
        const int d = ib * 8 + r;
        qreg[ib] = *reinterpret_cast<const float4*>(qg + (size_t)d * SQ + c4);
    }
    const uint4 cth = *reinterpret_cast<const uint4*>(g_ctxh + head * DH * DH + tid * 8);
    *reinterpret_cast<uint4*>(&sCt[tid >> 3][(tid & 7) * 8]) = cth;

    // exp(q) in f32 (Zq partials in float), pack to half
    float4 zp = make_float4(0.f, 0.f, 0.f, 0.f);
#pragma unroll
    for (int ib = 0; ib < 8; ++ib) {
        const int d = ib * 8 + r;
        float ex = __expf(qreg[ib].x);
        float ey = __expf(qreg[ib].y);
        float ez = __expf(qreg[ib].z);
        float ew = __expf(qreg[ib].w);
        zp.x += ex; zp.y += ey; zp.z += ez; zp.w += ew;
        uint2 eq;
        eq.x = pack_h2(ey, ex);
        eq.y = pack_h2(ew, ez);
        *reinterpret_cast<uint2*>(&sQ[d][c4]) = eq;
    }
    *reinterpret_cast<float4*>(&sZp[r][c4]) = zp;
    __syncthreads();

    // Zq reduce: 256 threads, one column each
    if (tid < 256) {
        float z = 0.0f;
#pragma unroll
        for (int d = 0; d < 8; ++d) z += sZp[d][tid];
        sCs[tid] = __fdividef(1.0f, z);
    }

    float acc[8][4];
#pragma unroll
    for (int n = 0; n < 8; ++n)
#pragma unroll
        for (int c = 0; c < 4; ++c) acc[n][c] = 0.0f;

    const int jw = (warp & 3) * 16;    // j offset
    const int sw = (warp >> 2) * 64;   // s offset

#pragma unroll
    for (int kk = 0; kk < 4; ++kk) {
        uint32_t a[4];
        ldsm_x4t(a, smem_u32(&sCt[kk * 16 + (lane & 7) + (lane >> 4) * 8]
                                [jw + ((lane >> 3) & 1) * 8]));
#pragma unroll
        for (int np = 0; np < 4; ++np) {
            uint32_t b[4];
            ldsm_x4t(b, smem_u32(&sQ[kk * 16 + (lane & 7) + ((lane >> 3) & 1) * 8]
                                    [sw + (np * 2 + (lane >> 4)) * 8]));
            mma_f16(acc[np * 2],     a, b);
            mma_f16(acc[np * 2 + 1], a, b + 2);
        }
    }
    __syncthreads();   // sCs ready (reduce overlapped with MMA issue)

    float* og = out + (size_t)head * DH * SQ + s0;
    const int j0 = jw + (lane >> 2);
    const int sc = (lane & 3) * 2;
#pragma unroll
    for (int n = 0; n < 8; ++n) {
        const int s = sw + n * 8 + sc;
        const float inv0 = sCs[s];
        const float inv1 = sCs[s + 1];
        float2 w0 = make_float2(acc[n][0] * inv0, acc[n][1] * inv1);
        float2 w1 = make_float2(acc[n][2] * inv0, acc[n][3] * inv1);
        *reinterpret_cast<float2*>(og + (size_t)j0 * SQ + s) = w0;
        *reinterpret_cast<float2*>(og + (size_t)(j0 + 8) * SQ + s) = w1;
    }
}

// ---------------------------------------------------------------------------
extern "C" void kernel_launch(void* const* d_in, const int* in_sizes, int n_in,
                              void* d_out, int out_size) {
    const float* q = (const float*)d_in[0];
    const float* k = (const float*)d_in[1];
    const float* v = (const float*)d_in[2];
    float* out = (float*)d_out;

    void* ctx_ptr = nullptr;
    void* zk_ptr  = nullptr;
    cudaGetSymbolAddress(&ctx_ptr, g_ctx);
    cudaGetSymbolAddress(&zk_ptr, g_zk);
    cudaMemsetAsync(ctx_ptr, 0, NHEADS * DH * DH * sizeof(float));
    cudaMemsetAsync(zk_ptr, 0, NHEADS * DH * sizeof(float));

    ctx_kernel<<<dim3(CHUNKS, NHEADS), 128>>>(k, v);
    norm_kernel<<<NHEADS, 128>>>();
    out_kernel<<<dim3(SQ / 256, NHEADS), 512>>>(q, out);
}